// round 2
// baseline (speedup 1.0000x reference)
#include <cuda_runtime.h>
#include <math.h>
#include <stdint.h>

// ---------------------------------------------------------------------------
// Problem constants (fixed by reference setup_inputs)
// ---------------------------------------------------------------------------
#define N_NODES 50000
#define E_EDGES 800000
constexpr int EW_BLOCKS = (E_EDGES + 255) / 256;   // 3125

// ---------------------------------------------------------------------------
// Static device scratch (allocation-free rule: __device__ globals)
// ---------------------------------------------------------------------------
__device__ float  g_h1[N_NODES * 512];      // MLP hidden 1
__device__ float  g_h2[N_NODES * 64];       // MLP hidden 2
__device__ float  g_logits[N_NODES * 64];
__device__ float  g_logitsP[N_NODES * 64];  // logits @ P
__device__ float  g_hA[N_NODES * 128];      // x0 / hcur ping
__device__ float  g_hB[N_NODES * 128];      // hcur pong
__device__ float  g_agg[N_NODES * 128];     // aggregation buffer
__device__ float  g_ew[E_EDGES];            // edge weights
__device__ float  g_P[64 * 64];             // relu(SCALE*parsing[0])
__device__ float  g_deg[N_NODES];
__device__ float  g_dinv[N_NODES];
__device__ double g_psum[EW_BLOCKS];
__device__ double g_psq[EW_BLOCKS];
__device__ float  g_ab[2];                  // scale a, offset b for ew norm

// ---------------------------------------------------------------------------
// Tiled SGEMM:  C[m,n] = act( alpha * (A@B)[m,n] + bias[n] + gamma*A[m,n] )
// BM=128, BN=64, BK=16, 256 threads, 8x4 register tile per thread.
// Requires: N % 64 == 0, K % 16 == 0. ADD_SRC requires N == K.
// ---------------------------------------------------------------------------
constexpr int BM = 128, BN = 64, BK = 16;

template<bool RELU, bool ADD_SRC>
__global__ __launch_bounds__(256) void sgemm_kernel(
    const float* __restrict__ A, const float* __restrict__ B,
    const float* __restrict__ bias, float* __restrict__ C,
    int M, int N, int K, float alpha, float gamma)
{
    __shared__ float As[BK][BM];
    __shared__ float Bs[BK][BN];

    const int tid  = threadIdx.x;
    const int m0   = blockIdx.x * BM;
    const int n0   = blockIdx.y * BN;
    const int trow = tid >> 4;   // 0..15 -> 8 rows each
    const int tcol = tid & 15;   // 0..15 -> 4 cols each

    float acc[8][4];
    #pragma unroll
    for (int r = 0; r < 8; r++)
        #pragma unroll
        for (int c = 0; c < 4; c++) acc[r][c] = 0.f;

    for (int k0 = 0; k0 < K; k0 += BK) {
        // --- load A tile (128x16) : 512 float4, 2 per thread, store transposed
        #pragma unroll
        for (int i = 0; i < 2; i++) {
            int t    = tid * 2 + i;      // 0..511
            int arow = t >> 2;           // 0..127
            int ac4  = t & 3;            // 0..3 (float4 within the 16-wide k slab)
            int m    = m0 + arow;
            float4 v = make_float4(0.f, 0.f, 0.f, 0.f);
            if (m < M)
                v = *reinterpret_cast<const float4*>(&A[(size_t)m * K + k0 + ac4 * 4]);
            As[ac4 * 4 + 0][arow] = v.x;
            As[ac4 * 4 + 1][arow] = v.y;
            As[ac4 * 4 + 2][arow] = v.z;
            As[ac4 * 4 + 3][arow] = v.w;
        }
        // --- load B tile (16x64) : 256 float4, 1 per thread
        {
            int brow = tid >> 4;     // 0..15
            int bc4  = tid & 15;     // 0..15
            float4 v = *reinterpret_cast<const float4*>(&B[(size_t)(k0 + brow) * N + n0 + bc4 * 4]);
            *reinterpret_cast<float4*>(&Bs[brow][bc4 * 4]) = v;
        }
        __syncthreads();

        #pragma unroll
        for (int kk = 0; kk < BK; kk++) {
            float4 a0 = *reinterpret_cast<const float4*>(&As[kk][trow * 8]);
            float4 a1 = *reinterpret_cast<const float4*>(&As[kk][trow * 8 + 4]);
            float4 b0 = *reinterpret_cast<const float4*>(&Bs[kk][tcol * 4]);
            float ra[8] = {a0.x, a0.y, a0.z, a0.w, a1.x, a1.y, a1.z, a1.w};
            float rb[4] = {b0.x, b0.y, b0.z, b0.w};
            #pragma unroll
            for (int r = 0; r < 8; r++)
                #pragma unroll
                for (int c = 0; c < 4; c++)
                    acc[r][c] = fmaf(ra[r], rb[c], acc[r][c]);
        }
        __syncthreads();
    }

    // --- epilogue
    float bb[4] = {0.f, 0.f, 0.f, 0.f};
    if (bias) {
        #pragma unroll
        for (int c = 0; c < 4; c++) bb[c] = bias[n0 + tcol * 4 + c];
    }
    #pragma unroll
    for (int r = 0; r < 8; r++) {
        int m = m0 + trow * 8 + r;
        if (m < M) {
            float v[4];
            #pragma unroll
            for (int c = 0; c < 4; c++) v[c] = alpha * acc[r][c] + bb[c];
            if (ADD_SRC) {  // N == K guaranteed by caller
                float4 s = *reinterpret_cast<const float4*>(&A[(size_t)m * K + n0 + tcol * 4]);
                v[0] += gamma * s.x; v[1] += gamma * s.y;
                v[2] += gamma * s.z; v[3] += gamma * s.w;
            }
            if (RELU) {
                #pragma unroll
                for (int c = 0; c < 4; c++) v[c] = fmaxf(v[c], 0.f);
            }
            *reinterpret_cast<float4*>(&C[(size_t)m * N + n0 + tcol * 4]) =
                make_float4(v[0], v[1], v[2], v[3]);
        }
    }
}

// ---------------------------------------------------------------------------
// P = relu(SCALE * parsing[0])
// ---------------------------------------------------------------------------
__global__ void relu_p_kernel(const float* __restrict__ parsing)
{
    int i = blockIdx.x * blockDim.x + threadIdx.x;
    if (i < 64 * 64) g_P[i] = fmaxf(2.0f * parsing[i], 0.f);
}

// ---------------------------------------------------------------------------
// ew[e] = dot64(logits[row[e]], logitsP[col[e]]), plus block partial sums
// ---------------------------------------------------------------------------
__global__ __launch_bounds__(256) void ew_kernel(const int* __restrict__ ei)
{
    int tid = threadIdx.x;
    int e   = blockIdx.x * 256 + tid;
    float v = 0.f;
    if (e < E_EDGES) {
        int r = ei[e];
        int c = ei[E_EDGES + e];
        const float4* lr = reinterpret_cast<const float4*>(g_logits  + (size_t)r * 64);
        const float4* lc = reinterpret_cast<const float4*>(g_logitsP + (size_t)c * 64);
        #pragma unroll
        for (int i = 0; i < 16; i++) {
            float4 a = lr[i], b = lc[i];
            v = fmaf(a.x, b.x, v); v = fmaf(a.y, b.y, v);
            v = fmaf(a.z, b.z, v); v = fmaf(a.w, b.w, v);
        }
        g_ew[e] = v;
    }
    __shared__ double ss[256];
    __shared__ double sq[256];
    ss[tid] = (double)v;
    sq[tid] = (double)v * (double)v;
    __syncthreads();
    #pragma unroll
    for (int s = 128; s > 0; s >>= 1) {
        if (tid < s) { ss[tid] += ss[tid + s]; sq[tid] += sq[tid + s]; }
        __syncthreads();
    }
    if (tid == 0) { g_psum[blockIdx.x] = ss[0]; g_psq[blockIdx.x] = sq[0]; }
}

// Deterministic final reduce -> a = sqrt(1e-4/var), b = 1 - a*mean
__global__ __launch_bounds__(256) void stats_kernel()
{
    int tid = threadIdx.x;
    double s = 0.0, q = 0.0;
    for (int i = tid; i < EW_BLOCKS; i += 256) { s += g_psum[i]; q += g_psq[i]; }
    __shared__ double ss[256];
    __shared__ double sq[256];
    ss[tid] = s; sq[tid] = q;
    __syncthreads();
    #pragma unroll
    for (int st = 128; st > 0; st >>= 1) {
        if (tid < st) { ss[tid] += ss[tid + st]; sq[tid] += sq[tid + st]; }
        __syncthreads();
    }
    if (tid == 0) {
        double sum  = ss[0], sumsq = sq[0];
        double mean = sum / (double)E_EDGES;
        double var  = (sumsq - sum * sum / (double)E_EDGES) / (double)(E_EDGES - 1);
        float  a    = sqrtf(1e-4f / (float)var);
        g_ab[0] = a;
        g_ab[1] = 1.0f - a * (float)mean;
    }
}

// deg[i] = 1 (self-loop weight)
__global__ void deg_init_kernel()
{
    int i = blockIdx.x * blockDim.x + threadIdx.x;
    if (i < N_NODES) g_deg[i] = 1.0f;
}

// ew normalize in place + accumulate degree at col
__global__ __launch_bounds__(256) void ew_finalize_kernel(const int* __restrict__ ei)
{
    int e = blockIdx.x * blockDim.x + threadIdx.x;
    if (e < E_EDGES) {
        float w = g_ab[0] * g_ew[e] + g_ab[1];
        g_ew[e] = w;
        atomicAdd(&g_deg[ei[E_EDGES + e]], w);
    }
}

__global__ void dinv_kernel()
{
    int i = blockIdx.x * blockDim.x + threadIdx.x;
    if (i < N_NODES) {
        float d = g_deg[i];
        g_dinv[i] = (d > 0.f) ? rsqrtf(d) : 0.f;
    }
}

// agg init = self-loop term: agg[i,:] = dinv[i]^2 * hcur[i,:]
__global__ __launch_bounds__(256) void self_agg_kernel(const float* __restrict__ hcur)
{
    int idx = blockIdx.x * blockDim.x + threadIdx.x;   // over N*32 float4s
    if (idx < N_NODES * 32) {
        int i = idx >> 5;
        float s = g_dinv[i];
        s = s * s;
        float4 h = reinterpret_cast<const float4*>(hcur)[idx];
        reinterpret_cast<float4*>(g_agg)[idx] =
            make_float4(s * h.x, s * h.y, s * h.z, s * h.w);
    }
}

// warp-per-edge scatter: agg[col] += dinv[row]*ew*dinv[col] * hcur[row]
__global__ __launch_bounds__(256) void scatter_kernel(const int* __restrict__ ei,
                                                      const float* __restrict__ hcur)
{
    int gid  = blockIdx.x * blockDim.x + threadIdx.x;
    int e    = gid >> 5;
    int lane = gid & 31;
    if (e < E_EDGES) {
        int r = ei[e];
        int c = ei[E_EDGES + e];
        float co = g_dinv[r] * g_ew[e] * g_dinv[c];
        float4 h = reinterpret_cast<const float4*>(hcur)[(size_t)r * 32 + lane];
        float* dst = g_agg + (size_t)c * 128 + lane * 4;
        atomicAdd(dst + 0, co * h.x);
        atomicAdd(dst + 1, co * h.y);
        atomicAdd(dst + 2, co * h.z);
        atomicAdd(dst + 3, co * h.w);
    }
}

// ---------------------------------------------------------------------------
// Host launcher
// ---------------------------------------------------------------------------
static void launch_sgemm(bool relu, bool add_src,
                         const float* A, const float* B, const float* bias, float* C,
                         int M, int N, int K, float alpha, float gamma)
{
    dim3 grid((M + BM - 1) / BM, N / BN);
    if (relu && add_src)
        sgemm_kernel<true, true><<<grid, 256>>>(A, B, bias, C, M, N, K, alpha, gamma);
    else if (relu)
        sgemm_kernel<true, false><<<grid, 256>>>(A, B, bias, C, M, N, K, alpha, gamma);
    else
        sgemm_kernel<false, false><<<grid, 256>>>(A, B, bias, C, M, N, K, alpha, gamma);
}

extern "C" void kernel_launch(void* const* d_in, const int* in_sizes, int n_in,
                              void* d_out, int out_size)
{
    const float* x       = (const float*)d_in[0];
    const int*   ei      = (const int*)  d_in[1];
    const float* mlp_w1  = (const float*)d_in[2];
    const float* mlp_b1  = (const float*)d_in[3];
    const float* mlp_w2  = (const float*)d_in[4];
    const float* mlp_b2  = (const float*)d_in[5];
    const float* mlp_w3  = (const float*)d_in[6];
    const float* mlp_b3  = (const float*)d_in[7];
    const float* parsing = (const float*)d_in[8];
    const float* lin0_w  = (const float*)d_in[9];
    const float* lin0_b  = (const float*)d_in[10];
    const float* lin1_w  = (const float*)d_in[11];
    const float* lin1_b  = (const float*)d_in[12];
    const float* conv_w1 = (const float*)d_in[13];
    // conv_w2 (d_in[14]) is multiplied by alpha*x0 = 0 in the reference -> unused
    float* out = (float*)d_out;

    // scratch pointers
    float *p_h1, *p_h2, *p_logits, *p_logitsP, *p_hA, *p_hB, *p_agg, *p_P;
    cudaGetSymbolAddress((void**)&p_h1,      g_h1);
    cudaGetSymbolAddress((void**)&p_h2,      g_h2);
    cudaGetSymbolAddress((void**)&p_logits,  g_logits);
    cudaGetSymbolAddress((void**)&p_logitsP, g_logitsP);
    cudaGetSymbolAddress((void**)&p_hA,      g_hA);
    cudaGetSymbolAddress((void**)&p_hB,      g_hB);
    cudaGetSymbolAddress((void**)&p_agg,     g_agg);
    cudaGetSymbolAddress((void**)&p_P,       g_P);

    const int M = N_NODES;
    const float beta0 = (float)log(2.0);   // log(THETA/1 + 1)
    const float beta1 = (float)log(1.5);   // log(THETA/2 + 1)

    // --- P = relu(2*parsing[0])
    relu_p_kernel<<<(64 * 64 + 255) / 256, 256>>>(parsing);

    // --- MLP edge scorer
    launch_sgemm(true,  false, x,     mlp_w1, mlp_b1, p_h1,     M, 512, 128, 1.f, 0.f);
    launch_sgemm(true,  false, p_h1,  mlp_w2, mlp_b2, p_h2,     M,  64, 512, 1.f, 0.f);
    launch_sgemm(false, false, p_h2,  mlp_w3, mlp_b3, p_logits, M,  64,  64, 1.f, 0.f);
    launch_sgemm(false, false, p_logits, p_P, nullptr, p_logitsP, M, 64, 64, 1.f, 0.f);

    // --- x0 = relu(x @ lin0 + b)
    launch_sgemm(true,  false, x, lin0_w, lin0_b, p_hA, M, 128, 128, 1.f, 0.f);

    // --- edge weights + normalization stats
    ew_kernel<<<EW_BLOCKS, 256>>>(ei);
    stats_kernel<<<1, 256>>>();
    deg_init_kernel<<<(N_NODES + 255) / 256, 256>>>();
    ew_finalize_kernel<<<(E_EDGES + 255) / 256, 256>>>(ei);
    dinv_kernel<<<(N_NODES + 255) / 256, 256>>>();

    // --- GCN2 layer 0: hA -> agg -> hB
    self_agg_kernel<<<(N_NODES * 32 + 255) / 256, 256>>>(p_hA);
    scatter_kernel<<<(E_EDGES * 32 + 255) / 256, 256>>>(ei, p_hA);
    launch_sgemm(true, true, p_agg, conv_w1, nullptr, p_hB,
                 M, 128, 128, beta0, 1.f - beta0);

    // --- GCN2 layer 1: hB -> agg -> hA
    self_agg_kernel<<<(N_NODES * 32 + 255) / 256, 256>>>(p_hB);
    scatter_kernel<<<(E_EDGES * 32 + 255) / 256, 256>>>(ei, p_hB);
    launch_sgemm(true, true, p_agg, conv_w1 + 128 * 128, nullptr, p_hA,
                 M, 128, 128, beta1, 1.f - beta1);

    // --- final projection -> d_out
    launch_sgemm(false, false, p_hA, lin1_w, lin1_b, out, M, 64, 128, 1.f, 0.f);

    (void)in_sizes; (void)n_in; (void)out_size;
}

// round 3
// speedup vs baseline: 1.3991x; 1.3991x over previous
#include <cuda_runtime.h>
#include <math.h>
#include <stdint.h>

// ---------------------------------------------------------------------------
// Problem constants (fixed by reference setup_inputs)
// ---------------------------------------------------------------------------
#define N_NODES 50000
#define E_EDGES 800000
constexpr int EW_BLOCKS = (E_EDGES + 255) / 256;   // 3125

// ---------------------------------------------------------------------------
// Static device scratch
// ---------------------------------------------------------------------------
__device__ float  g_h1[N_NODES * 512];
__device__ float  g_h2[N_NODES * 64];
__device__ float  g_logits[N_NODES * 64];
__device__ float  g_logitsP[N_NODES * 64];
__device__ float  g_hA[N_NODES * 128];
__device__ float  g_hB[N_NODES * 128];
__device__ float  g_agg[N_NODES * 128];
__device__ float  g_ew[E_EDGES];
__device__ float  g_P[64 * 64];
__device__ float  g_deg[N_NODES];
__device__ float  g_dinv[N_NODES];
__device__ double g_psum[EW_BLOCKS];
__device__ double g_psq[EW_BLOCKS];
__device__ float  g_ab[2];

// ---------------------------------------------------------------------------
// TF32 helpers
// ---------------------------------------------------------------------------
__device__ __forceinline__ uint32_t f2tf(float v) {
    uint32_t r;
    asm("cvt.rna.tf32.f32 %0, %1;" : "=r"(r) : "f"(v));
    return r;
}
__device__ __forceinline__ void split_tf32(float v, float& hi, float& lo) {
    float hf = __uint_as_float(f2tf(v));
    hi = hf;
    lo = __uint_as_float(f2tf(v - hf));
}

// ---------------------------------------------------------------------------
// TF32 tensor-core GEMM with 3-pass error compensation.
// C[m,n] = act( alpha*(A@B)[m,n] + bias[n] + gamma*A[m,n] )
// BM=128, BN=64, BK=16; 256 threads = 8 warps; warp tile 32x32 via
// m16n8k8 mma (2 m-tiles x 4 n-tiles). Requires N%64==0, K%16==0.
// ADD_SRC requires N==K.
// ---------------------------------------------------------------------------
constexpr int BM = 128, BN = 64, BK = 16;
constexpr int APAD = 20;   // As row stride (floats): bank=(20m+k)%32 conflict-free
constexpr int BPAD = 68;   // Bs row stride (floats): <=2-way conflicts

__device__ __forceinline__ void mma_tf32(float d[4], const uint32_t a[4],
                                         const uint32_t b[2]) {
    asm volatile(
        "mma.sync.aligned.m16n8k8.row.col.f32.tf32.tf32.f32 "
        "{%0,%1,%2,%3}, {%4,%5,%6,%7}, {%8,%9}, {%0,%1,%2,%3};"
        : "+f"(d[0]), "+f"(d[1]), "+f"(d[2]), "+f"(d[3])
        : "r"(a[0]), "r"(a[1]), "r"(a[2]), "r"(a[3]), "r"(b[0]), "r"(b[1]));
}

template<bool RELU, bool ADD_SRC>
__global__ __launch_bounds__(256) void tf32_gemm_kernel(
    const float* __restrict__ A, const float* __restrict__ B,
    const float* __restrict__ bias, float* __restrict__ C,
    int M, int N, int K, float alpha, float gamma)
{
    __shared__ float Ahi[BM * APAD];
    __shared__ float Alo[BM * APAD];
    __shared__ float Bhi[BK * BPAD];
    __shared__ float Blo[BK * BPAD];

    const int tid  = threadIdx.x;
    const int lane = tid & 31;
    const int warp = tid >> 5;
    const int wm0  = (warp >> 1) * 32;   // warp row offset in tile
    const int wn0  = (warp & 1) * 32;    // warp col offset in tile
    const int m0   = blockIdx.x * BM;
    const int n0   = blockIdx.y * BN;

    float d[2][4][4];
    #pragma unroll
    for (int mt = 0; mt < 2; mt++)
        #pragma unroll
        for (int nt = 0; nt < 4; nt++)
            #pragma unroll
            for (int r = 0; r < 4; r++) d[mt][nt][r] = 0.f;

    const int tr = lane >> 2;   // 0..7
    const int tk = lane & 3;    // 0..3

    for (int k0 = 0; k0 < K; k0 += BK) {
        // --- A tile (128x16): 512 float4, 2 per thread
        #pragma unroll
        for (int i = 0; i < 2; i++) {
            int f   = tid + i * 256;
            int row = f >> 2;
            int c4  = (f & 3) * 4;
            float4 v = make_float4(0.f, 0.f, 0.f, 0.f);
            if (m0 + row < M)
                v = *reinterpret_cast<const float4*>(&A[(size_t)(m0 + row) * K + k0 + c4]);
            float4 h, l;
            split_tf32(v.x, h.x, l.x); split_tf32(v.y, h.y, l.y);
            split_tf32(v.z, h.z, l.z); split_tf32(v.w, h.w, l.w);
            *reinterpret_cast<float4*>(&Ahi[row * APAD + c4]) = h;
            *reinterpret_cast<float4*>(&Alo[row * APAD + c4]) = l;
        }
        // --- B tile (16x64): 256 float4, 1 per thread
        {
            int kr = tid >> 4;
            int c4 = (tid & 15) * 4;
            float4 v = *reinterpret_cast<const float4*>(&B[(size_t)(k0 + kr) * N + n0 + c4]);
            float4 h, l;
            split_tf32(v.x, h.x, l.x); split_tf32(v.y, h.y, l.y);
            split_tf32(v.z, h.z, l.z); split_tf32(v.w, h.w, l.w);
            *reinterpret_cast<float4*>(&Bhi[kr * BPAD + c4]) = h;
            *reinterpret_cast<float4*>(&Blo[kr * BPAD + c4]) = l;
        }
        __syncthreads();

        #pragma unroll
        for (int ks = 0; ks < 2; ks++) {
            const int kb = ks * 8;
            uint32_t ah[2][4], al[2][4], bh[4][2], bl[4][2];
            #pragma unroll
            for (int mt = 0; mt < 2; mt++) {
                int r = wm0 + mt * 16 + tr;
                ah[mt][0] = __float_as_uint(Ahi[r * APAD + kb + tk]);
                ah[mt][1] = __float_as_uint(Ahi[(r + 8) * APAD + kb + tk]);
                ah[mt][2] = __float_as_uint(Ahi[r * APAD + kb + tk + 4]);
                ah[mt][3] = __float_as_uint(Ahi[(r + 8) * APAD + kb + tk + 4]);
                al[mt][0] = __float_as_uint(Alo[r * APAD + kb + tk]);
                al[mt][1] = __float_as_uint(Alo[(r + 8) * APAD + kb + tk]);
                al[mt][2] = __float_as_uint(Alo[r * APAD + kb + tk + 4]);
                al[mt][3] = __float_as_uint(Alo[(r + 8) * APAD + kb + tk + 4]);
            }
            #pragma unroll
            for (int nt = 0; nt < 4; nt++) {
                int n = wn0 + nt * 8 + tr;
                bh[nt][0] = __float_as_uint(Bhi[(kb + tk) * BPAD + n]);
                bh[nt][1] = __float_as_uint(Bhi[(kb + 4 + tk) * BPAD + n]);
                bl[nt][0] = __float_as_uint(Blo[(kb + tk) * BPAD + n]);
                bl[nt][1] = __float_as_uint(Blo[(kb + 4 + tk) * BPAD + n]);
            }
            #pragma unroll
            for (int mt = 0; mt < 2; mt++)
                #pragma unroll
                for (int nt = 0; nt < 4; nt++) {
                    mma_tf32(d[mt][nt], ah[mt], bh[nt]);
                    mma_tf32(d[mt][nt], ah[mt], bl[nt]);
                    mma_tf32(d[mt][nt], al[mt], bh[nt]);
                }
        }
        __syncthreads();
    }

    // --- epilogue
    #pragma unroll
    for (int mt = 0; mt < 2; mt++) {
        #pragma unroll
        for (int nt = 0; nt < 4; nt++) {
            int col  = n0 + wn0 + nt * 8 + tk * 2;
            float b0 = 0.f, b1 = 0.f;
            if (bias) { b0 = bias[col]; b1 = bias[col + 1]; }
            #pragma unroll
            for (int half = 0; half < 2; half++) {
                int row = m0 + wm0 + mt * 16 + tr + half * 8;
                if (row < M) {
                    float v0 = alpha * d[mt][nt][half * 2 + 0] + b0;
                    float v1 = alpha * d[mt][nt][half * 2 + 1] + b1;
                    if (ADD_SRC) {
                        float2 s = *reinterpret_cast<const float2*>(&A[(size_t)row * K + col]);
                        v0 += gamma * s.x;
                        v1 += gamma * s.y;
                    }
                    if (RELU) { v0 = fmaxf(v0, 0.f); v1 = fmaxf(v1, 0.f); }
                    *reinterpret_cast<float2*>(&C[(size_t)row * N + col]) = make_float2(v0, v1);
                }
            }
        }
    }
}

// ---------------------------------------------------------------------------
// P = relu(SCALE * parsing[0])
// ---------------------------------------------------------------------------
__global__ void relu_p_kernel(const float* __restrict__ parsing)
{
    int i = blockIdx.x * blockDim.x + threadIdx.x;
    if (i < 64 * 64) g_P[i] = fmaxf(2.0f * parsing[i], 0.f);
}

// ---------------------------------------------------------------------------
// ew[e] = dot64(logits[row[e]], logitsP[col[e]]), plus block partial sums
// ---------------------------------------------------------------------------
__global__ __launch_bounds__(256) void ew_kernel(const int* __restrict__ ei)
{
    int tid = threadIdx.x;
    int e   = blockIdx.x * 256 + tid;
    float v = 0.f;
    if (e < E_EDGES) {
        int r = ei[e];
        int c = ei[E_EDGES + e];
        const float4* lr = reinterpret_cast<const float4*>(g_logits  + (size_t)r * 64);
        const float4* lc = reinterpret_cast<const float4*>(g_logitsP + (size_t)c * 64);
        #pragma unroll
        for (int i = 0; i < 16; i++) {
            float4 a = lr[i], b = lc[i];
            v = fmaf(a.x, b.x, v); v = fmaf(a.y, b.y, v);
            v = fmaf(a.z, b.z, v); v = fmaf(a.w, b.w, v);
        }
        g_ew[e] = v;
    }
    __shared__ double ss[256];
    __shared__ double sq[256];
    ss[tid] = (double)v;
    sq[tid] = (double)v * (double)v;
    __syncthreads();
    #pragma unroll
    for (int s = 128; s > 0; s >>= 1) {
        if (tid < s) { ss[tid] += ss[tid + s]; sq[tid] += sq[tid + s]; }
        __syncthreads();
    }
    if (tid == 0) { g_psum[blockIdx.x] = ss[0]; g_psq[blockIdx.x] = sq[0]; }
}

__global__ __launch_bounds__(256) void stats_kernel()
{
    int tid = threadIdx.x;
    double s = 0.0, q = 0.0;
    for (int i = tid; i < EW_BLOCKS; i += 256) { s += g_psum[i]; q += g_psq[i]; }
    __shared__ double ss[256];
    __shared__ double sq[256];
    ss[tid] = s; sq[tid] = q;
    __syncthreads();
    #pragma unroll
    for (int st = 128; st > 0; st >>= 1) {
        if (tid < st) { ss[tid] += ss[tid + st]; sq[tid] += sq[tid + st]; }
        __syncthreads();
    }
    if (tid == 0) {
        double sum  = ss[0], sumsq = sq[0];
        double mean = sum / (double)E_EDGES;
        double var  = (sumsq - sum * sum / (double)E_EDGES) / (double)(E_EDGES - 1);
        float  a    = sqrtf(1e-4f / (float)var);
        g_ab[0] = a;
        g_ab[1] = 1.0f - a * (float)mean;
    }
}

__global__ void deg_init_kernel()
{
    int i = blockIdx.x * blockDim.x + threadIdx.x;
    if (i < N_NODES) g_deg[i] = 1.0f;
}

__global__ __launch_bounds__(256) void ew_finalize_kernel(const int* __restrict__ ei)
{
    int e = blockIdx.x * blockDim.x + threadIdx.x;
    if (e < E_EDGES) {
        float w = g_ab[0] * g_ew[e] + g_ab[1];
        g_ew[e] = w;
        atomicAdd(&g_deg[ei[E_EDGES + e]], w);
    }
}

__global__ void dinv_kernel()
{
    int i = blockIdx.x * blockDim.x + threadIdx.x;
    if (i < N_NODES) {
        float d = g_deg[i];
        g_dinv[i] = (d > 0.f) ? rsqrtf(d) : 0.f;
    }
}

// agg init = self-loop term: agg[i,:] = dinv[i]^2 * hcur[i,:]
__global__ __launch_bounds__(256) void self_agg_kernel(const float* __restrict__ hcur)
{
    int idx = blockIdx.x * blockDim.x + threadIdx.x;
    if (idx < N_NODES * 32) {
        int i = idx >> 5;
        float s = g_dinv[i];
        s = s * s;
        float4 h = reinterpret_cast<const float4*>(hcur)[idx];
        reinterpret_cast<float4*>(g_agg)[idx] =
            make_float4(s * h.x, s * h.y, s * h.z, s * h.w);
    }
}

// warp-per-edge scatter with vectorized red: agg[col] += co * hcur[row]
__global__ __launch_bounds__(256) void scatter_kernel(const int* __restrict__ ei,
                                                      const float* __restrict__ hcur)
{
    int gid  = blockIdx.x * blockDim.x + threadIdx.x;
    int e    = gid >> 5;
    int lane = gid & 31;
    if (e < E_EDGES) {
        int r = ei[e];
        int c = ei[E_EDGES + e];
        float co = g_dinv[r] * g_ew[e] * g_dinv[c];
        float4 h = reinterpret_cast<const float4*>(hcur)[(size_t)r * 32 + lane];
        float4* dst = reinterpret_cast<float4*>(g_agg + (size_t)c * 128 + lane * 4);
        atomicAdd(dst, make_float4(co * h.x, co * h.y, co * h.z, co * h.w));
    }
}

// ---------------------------------------------------------------------------
// Host launcher
// ---------------------------------------------------------------------------
static void launch_gemm(bool relu, bool add_src,
                        const float* A, const float* B, const float* bias, float* C,
                        int M, int N, int K, float alpha, float gamma)
{
    dim3 grid((M + BM - 1) / BM, N / BN);
    if (relu && add_src)
        tf32_gemm_kernel<true, true><<<grid, 256>>>(A, B, bias, C, M, N, K, alpha, gamma);
    else if (relu)
        tf32_gemm_kernel<true, false><<<grid, 256>>>(A, B, bias, C, M, N, K, alpha, gamma);
    else
        tf32_gemm_kernel<false, false><<<grid, 256>>>(A, B, bias, C, M, N, K, alpha, gamma);
}

extern "C" void kernel_launch(void* const* d_in, const int* in_sizes, int n_in,
                              void* d_out, int out_size)
{
    const float* x       = (const float*)d_in[0];
    const int*   ei      = (const int*)  d_in[1];
    const float* mlp_w1  = (const float*)d_in[2];
    const float* mlp_b1  = (const float*)d_in[3];
    const float* mlp_w2  = (const float*)d_in[4];
    const float* mlp_b2  = (const float*)d_in[5];
    const float* mlp_w3  = (const float*)d_in[6];
    const float* mlp_b3  = (const float*)d_in[7];
    const float* parsing = (const float*)d_in[8];
    const float* lin0_w  = (const float*)d_in[9];
    const float* lin0_b  = (const float*)d_in[10];
    const float* lin1_w  = (const float*)d_in[11];
    const float* lin1_b  = (const float*)d_in[12];
    const float* conv_w1 = (const float*)d_in[13];
    float* out = (float*)d_out;

    float *p_h1, *p_h2, *p_logits, *p_logitsP, *p_hA, *p_hB, *p_agg, *p_P;
    cudaGetSymbolAddress((void**)&p_h1,      g_h1);
    cudaGetSymbolAddress((void**)&p_h2,      g_h2);
    cudaGetSymbolAddress((void**)&p_logits,  g_logits);
    cudaGetSymbolAddress((void**)&p_logitsP, g_logitsP);
    cudaGetSymbolAddress((void**)&p_hA,      g_hA);
    cudaGetSymbolAddress((void**)&p_hB,      g_hB);
    cudaGetSymbolAddress((void**)&p_agg,     g_agg);
    cudaGetSymbolAddress((void**)&p_P,       g_P);

    const int M = N_NODES;
    const float beta0 = (float)log(2.0);
    const float beta1 = (float)log(1.5);

    relu_p_kernel<<<(64 * 64 + 255) / 256, 256>>>(parsing);

    // --- MLP edge scorer
    launch_gemm(true,  false, x,     mlp_w1, mlp_b1, p_h1,     M, 512, 128, 1.f, 0.f);
    launch_gemm(true,  false, p_h1,  mlp_w2, mlp_b2, p_h2,     M,  64, 512, 1.f, 0.f);
    launch_gemm(false, false, p_h2,  mlp_w3, mlp_b3, p_logits, M,  64,  64, 1.f, 0.f);
    launch_gemm(false, false, p_logits, p_P, nullptr, p_logitsP, M, 64, 64, 1.f, 0.f);

    // --- x0 = relu(x @ lin0 + b)
    launch_gemm(true,  false, x, lin0_w, lin0_b, p_hA, M, 128, 128, 1.f, 0.f);

    // --- edge weights + normalization stats
    ew_kernel<<<EW_BLOCKS, 256>>>(ei);
    stats_kernel<<<1, 256>>>();
    deg_init_kernel<<<(N_NODES + 255) / 256, 256>>>();
    ew_finalize_kernel<<<(E_EDGES + 255) / 256, 256>>>(ei);
    dinv_kernel<<<(N_NODES + 255) / 256, 256>>>();

    // --- GCN2 layer 0
    self_agg_kernel<<<(N_NODES * 32 + 255) / 256, 256>>>(p_hA);
    scatter_kernel<<<(E_EDGES * 32 + 255) / 256, 256>>>(ei, p_hA);
    launch_gemm(true, true, p_agg, conv_w1, nullptr, p_hB,
                M, 128, 128, beta0, 1.f - beta0);

    // --- GCN2 layer 1
    self_agg_kernel<<<(N_NODES * 32 + 255) / 256, 256>>>(p_hB);
    scatter_kernel<<<(E_EDGES * 32 + 255) / 256, 256>>>(ei, p_hB);
    launch_gemm(true, true, p_agg, conv_w1 + 128 * 128, nullptr, p_hA,
                M, 128, 128, beta1, 1.f - beta1);

    // --- final projection -> d_out
    launch_gemm(false, false, p_hA, lin1_w, lin1_b, out, M, 64, 128, 1.f, 0.f);

    (void)in_sizes; (void)n_in; (void)out_size;
}

// round 4
// speedup vs baseline: 1.7138x; 1.2249x over previous
#include <cuda_runtime.h>
#include <math.h>
#include <stdint.h>

// ---------------------------------------------------------------------------
// Problem constants
// ---------------------------------------------------------------------------
#define N_NODES 50000
#define E_EDGES 800000
constexpr int EW_BLOCKS = (E_EDGES + 255) / 256;   // 3125

// ---------------------------------------------------------------------------
// Static device scratch
// ---------------------------------------------------------------------------
__device__ float  g_h1[N_NODES * 512];
__device__ float  g_h2[N_NODES * 64];
__device__ float  g_logits[N_NODES * 64];
__device__ float  g_logitsP[N_NODES * 64];
__device__ float  g_hA[N_NODES * 128];
__device__ float  g_hB[N_NODES * 128];
__device__ float  g_agg[N_NODES * 128];
__device__ float  g_ew[E_EDGES];
__device__ float  g_P[64 * 64];
__device__ float  g_deg[N_NODES];
__device__ float  g_dinv[N_NODES];
__device__ int    g_cnt[N_NODES];
__device__ int    g_ptr[N_NODES + 1];
__device__ int    g_cursor[N_NODES];
__device__ int2   g_ecsr[E_EDGES];          // {row, coef-as-int}
__device__ double g_psum[EW_BLOCKS];
__device__ double g_psq[EW_BLOCKS];
__device__ float  g_ab[2];

// ---------------------------------------------------------------------------
// TF32 helpers
// ---------------------------------------------------------------------------
__device__ __forceinline__ uint32_t f2tf(float v) {
    uint32_t r;
    asm("cvt.rna.tf32.f32 %0, %1;" : "=r"(r) : "f"(v));
    return r;
}
__device__ __forceinline__ void split_tf32(float v, float& hi, float& lo) {
    float hf = __uint_as_float(f2tf(v));
    hi = hf;
    lo = __uint_as_float(f2tf(v - hf));
}

// ---------------------------------------------------------------------------
// TF32 tensor-core GEMM. COMP=true: 3-pass hi/lo error compensation.
// C[m,n] = act( alpha*(A@B)[m,n] + bias[n] + gamma*A[m,n] )
// BM=128, BN=64, BK=16; 256 threads; warp tile 32x32 via m16n8k8.
// Requires N%64==0, K%16==0. ADD_SRC requires N==K.
// ---------------------------------------------------------------------------
constexpr int BM = 128, BN = 64, BK = 16;
constexpr int APAD = 20;
constexpr int BPAD = 68;

__device__ __forceinline__ void mma_tf32(float d[4], const uint32_t a[4],
                                         const uint32_t b[2]) {
    asm volatile(
        "mma.sync.aligned.m16n8k8.row.col.f32.tf32.tf32.f32 "
        "{%0,%1,%2,%3}, {%4,%5,%6,%7}, {%8,%9}, {%0,%1,%2,%3};"
        : "+f"(d[0]), "+f"(d[1]), "+f"(d[2]), "+f"(d[3])
        : "r"(a[0]), "r"(a[1]), "r"(a[2]), "r"(a[3]), "r"(b[0]), "r"(b[1]));
}

template<bool RELU, bool ADD_SRC, bool COMP>
__global__ __launch_bounds__(256) void tf32_gemm_kernel(
    const float* __restrict__ A, const float* __restrict__ B,
    const float* __restrict__ bias, float* __restrict__ C,
    int M, int N, int K, float alpha, float gamma)
{
    __shared__ float Ahi[BM * APAD];
    __shared__ float Bhi[BK * BPAD];
    __shared__ float Alo[COMP ? BM * APAD : 1];
    __shared__ float Blo[COMP ? BK * BPAD : 1];

    const int tid  = threadIdx.x;
    const int lane = tid & 31;
    const int warp = tid >> 5;
    const int wm0  = (warp >> 1) * 32;
    const int wn0  = (warp & 1) * 32;
    const int m0   = blockIdx.x * BM;
    const int n0   = blockIdx.y * BN;

    float d[2][4][4];
    #pragma unroll
    for (int mt = 0; mt < 2; mt++)
        #pragma unroll
        for (int nt = 0; nt < 4; nt++)
            #pragma unroll
            for (int r = 0; r < 4; r++) d[mt][nt][r] = 0.f;

    const int tr = lane >> 2;
    const int tk = lane & 3;

    for (int k0 = 0; k0 < K; k0 += BK) {
        // --- A tile (128x16)
        #pragma unroll
        for (int i = 0; i < 2; i++) {
            int f   = tid + i * 256;
            int row = f >> 2;
            int c4  = (f & 3) * 4;
            float4 v = make_float4(0.f, 0.f, 0.f, 0.f);
            if (m0 + row < M)
                v = *reinterpret_cast<const float4*>(&A[(size_t)(m0 + row) * K + k0 + c4]);
            if (COMP) {
                float4 h, l;
                split_tf32(v.x, h.x, l.x); split_tf32(v.y, h.y, l.y);
                split_tf32(v.z, h.z, l.z); split_tf32(v.w, h.w, l.w);
                *reinterpret_cast<float4*>(&Ahi[row * APAD + c4]) = h;
                *reinterpret_cast<float4*>(&Alo[row * APAD + c4]) = l;
            } else {
                float4 h;
                h.x = __uint_as_float(f2tf(v.x)); h.y = __uint_as_float(f2tf(v.y));
                h.z = __uint_as_float(f2tf(v.z)); h.w = __uint_as_float(f2tf(v.w));
                *reinterpret_cast<float4*>(&Ahi[row * APAD + c4]) = h;
            }
        }
        // --- B tile (16x64)
        {
            int kr = tid >> 4;
            int c4 = (tid & 15) * 4;
            float4 v = *reinterpret_cast<const float4*>(&B[(size_t)(k0 + kr) * N + n0 + c4]);
            if (COMP) {
                float4 h, l;
                split_tf32(v.x, h.x, l.x); split_tf32(v.y, h.y, l.y);
                split_tf32(v.z, h.z, l.z); split_tf32(v.w, h.w, l.w);
                *reinterpret_cast<float4*>(&Bhi[kr * BPAD + c4]) = h;
                *reinterpret_cast<float4*>(&Blo[kr * BPAD + c4]) = l;
            } else {
                float4 h;
                h.x = __uint_as_float(f2tf(v.x)); h.y = __uint_as_float(f2tf(v.y));
                h.z = __uint_as_float(f2tf(v.z)); h.w = __uint_as_float(f2tf(v.w));
                *reinterpret_cast<float4*>(&Bhi[kr * BPAD + c4]) = h;
            }
        }
        __syncthreads();

        #pragma unroll
        for (int ks = 0; ks < 2; ks++) {
            const int kb = ks * 8;
            uint32_t ah[2][4], bh[4][2];
            #pragma unroll
            for (int mt = 0; mt < 2; mt++) {
                int r = wm0 + mt * 16 + tr;
                ah[mt][0] = __float_as_uint(Ahi[r * APAD + kb + tk]);
                ah[mt][1] = __float_as_uint(Ahi[(r + 8) * APAD + kb + tk]);
                ah[mt][2] = __float_as_uint(Ahi[r * APAD + kb + tk + 4]);
                ah[mt][3] = __float_as_uint(Ahi[(r + 8) * APAD + kb + tk + 4]);
            }
            #pragma unroll
            for (int nt = 0; nt < 4; nt++) {
                int n = wn0 + nt * 8 + tr;
                bh[nt][0] = __float_as_uint(Bhi[(kb + tk) * BPAD + n]);
                bh[nt][1] = __float_as_uint(Bhi[(kb + 4 + tk) * BPAD + n]);
            }
            if (COMP) {
                uint32_t al[2][4], bl[4][2];
                #pragma unroll
                for (int mt = 0; mt < 2; mt++) {
                    int r = wm0 + mt * 16 + tr;
                    al[mt][0] = __float_as_uint(Alo[r * APAD + kb + tk]);
                    al[mt][1] = __float_as_uint(Alo[(r + 8) * APAD + kb + tk]);
                    al[mt][2] = __float_as_uint(Alo[r * APAD + kb + tk + 4]);
                    al[mt][3] = __float_as_uint(Alo[(r + 8) * APAD + kb + tk + 4]);
                }
                #pragma unroll
                for (int nt = 0; nt < 4; nt++) {
                    int n = wn0 + nt * 8 + tr;
                    bl[nt][0] = __float_as_uint(Blo[(kb + tk) * BPAD + n]);
                    bl[nt][1] = __float_as_uint(Blo[(kb + 4 + tk) * BPAD + n]);
                }
                #pragma unroll
                for (int mt = 0; mt < 2; mt++)
                    #pragma unroll
                    for (int nt = 0; nt < 4; nt++) {
                        mma_tf32(d[mt][nt], ah[mt], bh[nt]);
                        mma_tf32(d[mt][nt], ah[mt], bl[nt]);
                        mma_tf32(d[mt][nt], al[mt], bh[nt]);
                    }
            } else {
                #pragma unroll
                for (int mt = 0; mt < 2; mt++)
                    #pragma unroll
                    for (int nt = 0; nt < 4; nt++)
                        mma_tf32(d[mt][nt], ah[mt], bh[nt]);
            }
        }
        __syncthreads();
    }

    // --- epilogue
    #pragma unroll
    for (int mt = 0; mt < 2; mt++) {
        #pragma unroll
        for (int nt = 0; nt < 4; nt++) {
            int col  = n0 + wn0 + nt * 8 + tk * 2;
            float b0 = 0.f, b1 = 0.f;
            if (bias) { b0 = bias[col]; b1 = bias[col + 1]; }
            #pragma unroll
            for (int half = 0; half < 2; half++) {
                int row = m0 + wm0 + mt * 16 + tr + half * 8;
                if (row < M) {
                    float v0 = alpha * d[mt][nt][half * 2 + 0] + b0;
                    float v1 = alpha * d[mt][nt][half * 2 + 1] + b1;
                    if (ADD_SRC) {
                        float2 s = *reinterpret_cast<const float2*>(&A[(size_t)row * K + col]);
                        v0 += gamma * s.x;
                        v1 += gamma * s.y;
                    }
                    if (RELU) { v0 = fmaxf(v0, 0.f); v1 = fmaxf(v1, 0.f); }
                    *reinterpret_cast<float2*>(&C[(size_t)row * N + col]) = make_float2(v0, v1);
                }
            }
        }
    }
}

// ---------------------------------------------------------------------------
__global__ void relu_p_kernel(const float* __restrict__ parsing)
{
    int i = blockIdx.x * blockDim.x + threadIdx.x;
    if (i < 64 * 64) g_P[i] = fmaxf(2.0f * parsing[i], 0.f);
}

// ew[e] = dot64(logits[row[e]], logitsP[col[e]]), plus block partial sums
__global__ __launch_bounds__(256) void ew_kernel(const int* __restrict__ ei)
{
    int tid = threadIdx.x;
    int e   = blockIdx.x * 256 + tid;
    float v = 0.f;
    if (e < E_EDGES) {
        int r = ei[e];
        int c = ei[E_EDGES + e];
        const float4* lr = reinterpret_cast<const float4*>(g_logits  + (size_t)r * 64);
        const float4* lc = reinterpret_cast<const float4*>(g_logitsP + (size_t)c * 64);
        #pragma unroll
        for (int i = 0; i < 16; i++) {
            float4 a = lr[i], b = lc[i];
            v = fmaf(a.x, b.x, v); v = fmaf(a.y, b.y, v);
            v = fmaf(a.z, b.z, v); v = fmaf(a.w, b.w, v);
        }
        g_ew[e] = v;
    }
    __shared__ double ss[256];
    __shared__ double sq[256];
    ss[tid] = (double)v;
    sq[tid] = (double)v * (double)v;
    __syncthreads();
    #pragma unroll
    for (int s = 128; s > 0; s >>= 1) {
        if (tid < s) { ss[tid] += ss[tid + s]; sq[tid] += sq[tid + s]; }
        __syncthreads();
    }
    if (tid == 0) { g_psum[blockIdx.x] = ss[0]; g_psq[blockIdx.x] = sq[0]; }
}

__global__ __launch_bounds__(256) void stats_kernel()
{
    int tid = threadIdx.x;
    double s = 0.0, q = 0.0;
    for (int i = tid; i < EW_BLOCKS; i += 256) { s += g_psum[i]; q += g_psq[i]; }
    __shared__ double ss[256];
    __shared__ double sq[256];
    ss[tid] = s; sq[tid] = q;
    __syncthreads();
    #pragma unroll
    for (int st = 128; st > 0; st >>= 1) {
        if (tid < st) { ss[tid] += ss[tid + st]; sq[tid] += sq[tid + st]; }
        __syncthreads();
    }
    if (tid == 0) {
        double sum  = ss[0], sumsq = sq[0];
        double mean = sum / (double)E_EDGES;
        double var  = (sumsq - sum * sum / (double)E_EDGES) / (double)(E_EDGES - 1);
        float  a    = sqrtf(1e-4f / (float)var);
        g_ab[0] = a;
        g_ab[1] = 1.0f - a * (float)mean;
    }
}

// deg=1 (self loop), cnt=0
__global__ void init_deg_cnt_kernel()
{
    int i = blockIdx.x * blockDim.x + threadIdx.x;
    if (i < N_NODES) { g_deg[i] = 1.0f; g_cnt[i] = 0; }
}

// normalize ew in place + accumulate degree and count at col
__global__ __launch_bounds__(256) void ew_finalize_kernel(const int* __restrict__ ei)
{
    int e = blockIdx.x * blockDim.x + threadIdx.x;
    if (e < E_EDGES) {
        float w = g_ab[0] * g_ew[e] + g_ab[1];
        g_ew[e] = w;
        int c = ei[E_EDGES + e];
        atomicAdd(&g_deg[c], w);
        atomicAdd(&g_cnt[c], 1);
    }
}

__global__ void dinv_kernel()
{
    int i = blockIdx.x * blockDim.x + threadIdx.x;
    if (i < N_NODES) {
        float d = g_deg[i];
        g_dinv[i] = (d > 0.f) ? rsqrtf(d) : 0.f;
    }
}

// single-block exclusive scan over g_cnt -> g_ptr, g_cursor
__global__ __launch_bounds__(1024) void scan_kernel()
{
    __shared__ int partial[1024];
    const int t  = threadIdx.x;
    const int CH = (N_NODES + 1023) / 1024;  // 49
    const int base = t * CH;
    int s = 0;
    for (int i = 0; i < CH; i++) {
        int idx = base + i;
        if (idx < N_NODES) s += g_cnt[idx];
    }
    partial[t] = s;
    __syncthreads();
    for (int off = 1; off < 1024; off <<= 1) {
        int v = (t >= off) ? partial[t - off] : 0;
        __syncthreads();
        if (t >= off) partial[t] += v;
        __syncthreads();
    }
    int excl = (t == 0) ? 0 : partial[t - 1];
    for (int i = 0; i < CH; i++) {
        int idx = base + i;
        if (idx < N_NODES) {
            g_ptr[idx]    = excl;
            g_cursor[idx] = excl;
            excl += g_cnt[idx];
        }
    }
    if (t == 0) g_ptr[N_NODES] = E_EDGES;
}

// fill CSR entries: {row, coef = dinv[r]*ew*dinv[c]}
__global__ __launch_bounds__(256) void fill_kernel(const int* __restrict__ ei)
{
    int e = blockIdx.x * blockDim.x + threadIdx.x;
    if (e < E_EDGES) {
        int r = ei[e];
        int c = ei[E_EDGES + e];
        float co = g_dinv[r] * g_ew[e] * g_dinv[c];
        int pos = atomicAdd(&g_cursor[c], 1);
        g_ecsr[pos] = make_int2(r, __float_as_int(co));
    }
}

// warp-per-node gather: agg[i] = dinv[i]^2*hcur[i] + sum_j coef_j * hcur[row_j]
__global__ __launch_bounds__(256) void gather_kernel(const float* __restrict__ hcur)
{
    const int warp = threadIdx.x >> 5;
    const int lane = threadIdx.x & 31;
    const int node = blockIdx.x * 8 + warp;
    if (node >= N_NODES) return;

    float di = g_dinv[node];
    float s  = di * di;
    float4 h = reinterpret_cast<const float4*>(hcur)[(size_t)node * 32 + lane];
    float4 acc = make_float4(s * h.x, s * h.y, s * h.z, s * h.w);

    int j   = g_ptr[node];
    int end = g_ptr[node + 1];
    for (; j + 1 < end; j += 2) {
        int2 e0 = g_ecsr[j];
        int2 e1 = g_ecsr[j + 1];
        float c0 = __int_as_float(e0.y);
        float c1 = __int_as_float(e1.y);
        float4 v0 = reinterpret_cast<const float4*>(hcur)[(size_t)e0.x * 32 + lane];
        float4 v1 = reinterpret_cast<const float4*>(hcur)[(size_t)e1.x * 32 + lane];
        acc.x = fmaf(c0, v0.x, acc.x); acc.y = fmaf(c0, v0.y, acc.y);
        acc.z = fmaf(c0, v0.z, acc.z); acc.w = fmaf(c0, v0.w, acc.w);
        acc.x = fmaf(c1, v1.x, acc.x); acc.y = fmaf(c1, v1.y, acc.y);
        acc.z = fmaf(c1, v1.z, acc.z); acc.w = fmaf(c1, v1.w, acc.w);
    }
    if (j < end) {
        int2 e0 = g_ecsr[j];
        float c0 = __int_as_float(e0.y);
        float4 v0 = reinterpret_cast<const float4*>(hcur)[(size_t)e0.x * 32 + lane];
        acc.x = fmaf(c0, v0.x, acc.x); acc.y = fmaf(c0, v0.y, acc.y);
        acc.z = fmaf(c0, v0.z, acc.z); acc.w = fmaf(c0, v0.w, acc.w);
    }
    reinterpret_cast<float4*>(g_agg)[(size_t)node * 32 + lane] = acc;
}

// ---------------------------------------------------------------------------
// Host launcher
// ---------------------------------------------------------------------------
static void launch_gemm(bool relu, bool add_src, bool comp,
                        const float* A, const float* B, const float* bias, float* C,
                        int M, int N, int K, float alpha, float gamma)
{
    dim3 grid((M + BM - 1) / BM, N / BN);
    if (add_src) {        // always relu + comp in this pipeline
        tf32_gemm_kernel<true, true, true><<<grid, 256>>>(A, B, bias, C, M, N, K, alpha, gamma);
    } else if (comp) {
        if (relu) tf32_gemm_kernel<true,  false, true><<<grid, 256>>>(A, B, bias, C, M, N, K, alpha, gamma);
        else      tf32_gemm_kernel<false, false, true><<<grid, 256>>>(A, B, bias, C, M, N, K, alpha, gamma);
    } else {
        if (relu) tf32_gemm_kernel<true,  false, false><<<grid, 256>>>(A, B, bias, C, M, N, K, alpha, gamma);
        else      tf32_gemm_kernel<false, false, false><<<grid, 256>>>(A, B, bias, C, M, N, K, alpha, gamma);
    }
}

extern "C" void kernel_launch(void* const* d_in, const int* in_sizes, int n_in,
                              void* d_out, int out_size)
{
    const float* x       = (const float*)d_in[0];
    const int*   ei      = (const int*)  d_in[1];
    const float* mlp_w1  = (const float*)d_in[2];
    const float* mlp_b1  = (const float*)d_in[3];
    const float* mlp_w2  = (const float*)d_in[4];
    const float* mlp_b2  = (const float*)d_in[5];
    const float* mlp_w3  = (const float*)d_in[6];
    const float* mlp_b3  = (const float*)d_in[7];
    const float* parsing = (const float*)d_in[8];
    const float* lin0_w  = (const float*)d_in[9];
    const float* lin0_b  = (const float*)d_in[10];
    const float* lin1_w  = (const float*)d_in[11];
    const float* lin1_b  = (const float*)d_in[12];
    const float* conv_w1 = (const float*)d_in[13];
    float* out = (float*)d_out;

    float *p_h1, *p_h2, *p_logits, *p_logitsP, *p_hA, *p_hB, *p_agg, *p_P;
    cudaGetSymbolAddress((void**)&p_h1,      g_h1);
    cudaGetSymbolAddress((void**)&p_h2,      g_h2);
    cudaGetSymbolAddress((void**)&p_logits,  g_logits);
    cudaGetSymbolAddress((void**)&p_logitsP, g_logitsP);
    cudaGetSymbolAddress((void**)&p_hA,      g_hA);
    cudaGetSymbolAddress((void**)&p_hB,      g_hB);
    cudaGetSymbolAddress((void**)&p_agg,     g_agg);
    cudaGetSymbolAddress((void**)&p_P,       g_P);

    const int M = N_NODES;
    const float beta0 = (float)log(2.0);
    const float beta1 = (float)log(1.5);

    relu_p_kernel<<<(64 * 64 + 255) / 256, 256>>>(parsing);

    // --- MLP edge scorer (single-pass TF32: error absorbed by ew normalization)
    launch_gemm(true,  false, false, x,     mlp_w1, mlp_b1, p_h1,     M, 512, 128, 1.f, 0.f);
    launch_gemm(true,  false, false, p_h1,  mlp_w2, mlp_b2, p_h2,     M,  64, 512, 1.f, 0.f);
    launch_gemm(false, false, false, p_h2,  mlp_w3, mlp_b3, p_logits, M,  64,  64, 1.f, 0.f);
    launch_gemm(false, false, false, p_logits, p_P, nullptr, p_logitsP, M, 64, 64, 1.f, 0.f);

    // --- x0 = relu(x @ lin0 + b)  (3-pass: feeds output directly)
    launch_gemm(true,  false, true, x, lin0_w, lin0_b, p_hA, M, 128, 128, 1.f, 0.f);

    // --- edge weights + normalization stats + CSR build
    ew_kernel<<<EW_BLOCKS, 256>>>(ei);
    stats_kernel<<<1, 256>>>();
    init_deg_cnt_kernel<<<(N_NODES + 255) / 256, 256>>>();
    ew_finalize_kernel<<<(E_EDGES + 255) / 256, 256>>>(ei);
    dinv_kernel<<<(N_NODES + 255) / 256, 256>>>();
    scan_kernel<<<1, 1024>>>();
    fill_kernel<<<(E_EDGES + 255) / 256, 256>>>(ei);

    // --- GCN2 layer 0
    gather_kernel<<<(N_NODES + 7) / 8, 256>>>(p_hA);
    launch_gemm(true, true, true, p_agg, conv_w1, nullptr, p_hB,
                M, 128, 128, beta0, 1.f - beta0);

    // --- GCN2 layer 1
    gather_kernel<<<(N_NODES + 7) / 8, 256>>>(p_hB);
    launch_gemm(true, true, true, p_agg, conv_w1 + 128 * 128, nullptr, p_hA,
                M, 128, 128, beta1, 1.f - beta1);

    // --- final projection -> d_out
    launch_gemm(false, false, true, p_hA, lin1_w, lin1_b, out, M, 64, 128, 1.f, 0.f);

    (void)in_sizes; (void)n_in; (void)out_size;
}